// round 17
// baseline (speedup 1.0000x reference)
#include <cuda_runtime.h>

// MultiHeadAttention: B=4096, S=102, HIDDEN=8, HEADS=2, HEAD_DIM=4
// Attention thread owns 2 full query rows x BOTH heads (51 thr/batch, exact),
// so the output projection is folded into the attention epilogue (no outproj
// phase, no ao smem round-trip, one less barrier). Query-pair packed dots via
// dim-duplicated K. NB=7, NT=384, smem ~105KB -> 2 CTAs/SM, grid=586 -> 1.98 waves.

#define SQ   102
#define NB   7
#define NT   384
#define RS   28                    // floats per j-row (both heads, padded)

typedef unsigned long long u64;

__device__ __forceinline__ u64 pack2(float lo, float hi) {
    u64 r; asm("mov.b64 %0, {%1, %2};" : "=l"(r) : "f"(lo), "f"(hi)); return r;
}
__device__ __forceinline__ void unpack2(u64 v, float& lo, float& hi) {
    asm("mov.b64 {%0, %1}, %2;" : "=f"(lo), "=f"(hi) : "l"(v));
}
__device__ __forceinline__ u64 fma2(u64 a, u64 b, u64 c) {
    u64 d; asm("fma.rn.f32x2 %0, %1, %2, %3;" : "=l"(d) : "l"(a), "l"(b), "l"(c)); return d;
}
__device__ __forceinline__ u64 mul2(u64 a, u64 b) {
    u64 d; asm("mul.rn.f32x2 %0, %1, %2;" : "=l"(d) : "l"(a), "l"(b)); return d;
}
__device__ __forceinline__ u64 add2(u64 a, u64 b) {
    u64 d; asm("add.rn.f32x2 %0, %1, %2;" : "=l"(d) : "l"(a), "l"(b)); return d;
}
__device__ __forceinline__ float ex2f(float x) {
    float r; asm("ex2.approx.f32 %0, %1;" : "=f"(r) : "f"(x)); return r;
}

// dual 8-dot: d0 = x . w[row 2p], d1 = x . w[row 2p+1]; w rows are 4 u64 each.
__device__ __forceinline__ void dual_dot8(const u64* w, u64 xax, u64 xay,
                                          u64 xbx, u64 xby, float& d0, float& d1)
{
    u64 a0 = mul2(xax, w[0]);
    a0 = fma2(xay, w[1], a0);
    a0 = fma2(xbx, w[2], a0);
    a0 = fma2(xby, w[3], a0);
    u64 a1 = mul2(xax, w[4]);
    a1 = fma2(xay, w[5], a1);
    a1 = fma2(xbx, w[6], a1);
    a1 = fma2(xby, w[7], a1);
    float l0, h0, l1, h1;
    unpack2(a0, l0, h0); unpack2(a1, l1, h1);
    d0 = l0 + h0; d1 = l1 + h1;
}

__global__ __launch_bounds__(NT, 2) void mha_fused_kernel(
    const float* __restrict__ query, const float* __restrict__ key,
    const float* __restrict__ value, const float* __restrict__ wq,
    const float* __restrict__ wk,    const float* __restrict__ wv,
    const float* __restrict__ wo,    float* __restrict__ out, int nbatch)
{
    extern __shared__ __align__(16) char smraw[];
    float (*sw)[64]     = (float (*)[64])smraw;                 // [4][64]        1024 B
    float (*ms)[2]      = (float (*)[2])(smraw + 1024);         // [102][2]        816 B
    float (*qs)[SQ][8]  = (float (*)[SQ][8])(smraw + 1840);     // [NB][102][8]  22848 B
    float (*kvs)[SQ*RS] = (float (*)[SQ*RS])(smraw + 24688);    // [NB][2856]    79968 B

    const int tid = threadIdx.x;
    const int b0  = blockIdx.x * NB;

    // ---- weights -> shared ----
    if (tid < 256) {
        int w = tid >> 6, e = tid & 63;
        const float* src = (w == 0) ? wq : (w == 1) ? wk : (w == 2) ? wv : wo;
        sw[w][e] = src[e];
    }
    // ---- rotary multipliers (Cody-Waite reduction, robust under fast-math) ----
    if (tid >= 256 && tid < 256 + SQ) {
        float x = (float)(tid - 256);
        float k = rintf(x * 0.15915494309189535f);
        float r = fmaf(-k, 6.28125f, x);
        r = fmaf(-k, 0.0019353071795864769f, r);
        float s, c; sincosf(r, &s, &c);
        ms[tid - 256][0] = s; ms[tid - 256][1] = c;
    }
    __syncthreads();

    // ---- projections + rotary; one thread = one full row (8 outputs) ----
    // exp arg = (q.k)*0.5 -> exp2((q.k)*0.5*log2e); fold C into q projection.
    // K written dim-duplicated: row j: h0 kdup r64[0..3], v r64[4..5];
    //                                  h1 kdup r64[6..9], v r64[10..11].
    const float C = 0.72134752044448169f;   // 0.5 * log2(e)
    for (int i = tid; i < NB * 306; i += NT) {
        int nb  = i / 306;
        int rem = i - nb * 306;
        int b   = b0 + nb;
        if (b >= nbatch) continue;
        int t = rem / 102;                  // 0=q, 1=k, 2=v
        int s = rem - t * 102;
        const float* src = (t == 0) ? query : (t == 1) ? key : value;
        const ulonglong2* xr = (const ulonglong2*)(src + (size_t)b * 816 + s * 8);
        ulonglong2 xa = xr[0], xb = xr[1];
        float o[8];
        if (t < 2) {
            float msin = ms[s][0], mcos = ms[s][1];
            if (t == 0) { msin *= C; mcos *= C; }
            #pragma unroll
            for (int p = 0; p < 4; p++) {
                const u64* w = (const u64*)&sw[t][(2 * p) * 8];
                float d0, d1;
                dual_dot8(w, xa.x, xa.y, xb.x, xb.y, d0, d1);
                float m = (p < 2) ? msin : mcos;     // head0 -> sin, head1 -> cos
                o[2*p]   = (d0 - d1) * m;
                o[2*p+1] = (d1 + d0) * m;
            }
            if (t == 0) {
                float* dst = &qs[nb][s][0];
                *(float4*)dst       = make_float4(o[0], o[1], o[2], o[3]);
                *(float4*)(dst + 4) = make_float4(o[4], o[5], o[6], o[7]);
            } else {
                u64* r64 = (u64*)&kvs[nb][s * RS];
                r64[0] = pack2(o[0], o[0]); r64[1] = pack2(o[1], o[1]);
                r64[2] = pack2(o[2], o[2]); r64[3] = pack2(o[3], o[3]);
                r64[6] = pack2(o[4], o[4]); r64[7] = pack2(o[5], o[5]);
                r64[8] = pack2(o[6], o[6]); r64[9] = pack2(o[7], o[7]);
            }
        } else {
            #pragma unroll
            for (int p = 0; p < 4; p++) {
                const u64* w = (const u64*)&sw[2][(2 * p) * 8];
                dual_dot8(w, xa.x, xa.y, xb.x, xb.y, o[2*p], o[2*p+1]);
            }
            float* r = &kvs[nb][s * RS];
            *(float4*)(r + 8)  = make_float4(o[0], o[1], o[2], o[3]);
            *(float4*)(r + 20) = make_float4(o[4], o[5], o[6], o[7]);
        }
    }
    __syncthreads();

    // ---- attention + inline output projection ----
    // thread = (nb, query-pair qg): rows 2qg, 2qg+1, BOTH heads (51*2=102 exact).
    if (tid < NB * 51) {
        int nb = tid / 51;
        int qg = tid - nb * 51;
        int b  = b0 + nb;
        if (b < nbatch) {
            const int r0 = 2 * qg;
            // pack q: qp[h][d] = (q_r0[h4+d], q_r1[h4+d])
            const float* qa = &qs[nb][r0][0];
            const float* qb = &qs[nb][r0 + 1][0];
            u64 qp[2][4];
            #pragma unroll
            for (int h = 0; h < 2; h++)
                #pragma unroll
                for (int d = 0; d < 4; d++)
                    qp[h][d] = pack2(qa[h * 4 + d], qb[h * 4 + d]);

            u64 acc[2][2][2];   // [q][h][half]
            #pragma unroll
            for (int q = 0; q < 2; q++)
                #pragma unroll
                for (int h = 0; h < 2; h++)
                    acc[q][h][0] = acc[q][h][1] = 0ull;
            u64 sum[2] = {0ull, 0ull};   // per head, (q0,q1) packed

            const u64* kvb = (const u64*)&kvs[nb][0];
            #pragma unroll 2
            for (int j = 0; j < SQ; j++) {
                const u64* row = kvb + j * (RS / 2);
                #pragma unroll
                for (int h = 0; h < 2; h++) {
                    const u64* rh = row + h * 6;
                    u64 d = mul2(qp[h][0], rh[0]);
                    d = fma2(qp[h][1], rh[1], d);
                    d = fma2(qp[h][2], rh[2], d);
                    d = fma2(qp[h][3], rh[3], d);
                    float da, db; unpack2(d, da, db);
                    float ea = ex2f(da), eb = ex2f(db);
                    sum[h] = add2(sum[h], pack2(ea, eb));
                    u64 ead = pack2(ea, ea), ebd = pack2(eb, eb);
                    u64 v01 = rh[4], v23 = rh[5];
                    acc[0][h][0] = fma2(ead, v01, acc[0][h][0]);
                    acc[0][h][1] = fma2(ead, v23, acc[0][h][1]);
                    acc[1][h][0] = fma2(ebd, v01, acc[1][h][0]);
                    acc[1][h][1] = fma2(ebd, v23, acc[1][h][1]);
                }
            }

            // epilogue: normalize + output projection, all in registers
            float s00, s01, s10, s11;
            unpack2(sum[0], s00, s01);   // head0: q0, q1
            unpack2(sum[1], s10, s11);   // head1: q0, q1
            float i00 = 1.0f / s00, i01 = 1.0f / s01;
            float i10 = 1.0f / s10, i11 = 1.0f / s11;
            const u64* w = (const u64*)&sw[3][0];
            #pragma unroll
            for (int q = 0; q < 2; q++) {
                u64 inv0 = pack2(q ? i01 : i00, q ? i01 : i00);
                u64 inv1 = pack2(q ? i11 : i10, q ? i11 : i10);
                u64 xax = mul2(acc[q][0][0], inv0);
                u64 xay = mul2(acc[q][0][1], inv0);
                u64 xbx = mul2(acc[q][1][0], inv1);
                u64 xby = mul2(acc[q][1][1], inv1);
                float o[8];
                #pragma unroll
                for (int p = 0; p < 4; p++)
                    dual_dot8(w + p * 8, xax, xay, xbx, xby, o[2*p], o[2*p+1]);
                float4* dst = (float4*)(out + (size_t)b * 816 + (r0 + q) * 8);
                dst[0] = make_float4(o[0], o[1], o[2], o[3]);
                dst[1] = make_float4(o[4], o[5], o[6], o[7]);
            }
        }
    }
}

extern "C" void kernel_launch(void* const* d_in, const int* in_sizes, int n_in,
                              void* d_out, int out_size)
{
    const float* query = (const float*)d_in[0];
    const float* key   = (const float*)d_in[1];
    const float* value = (const float*)d_in[2];
    const float* wq    = (const float*)d_in[3];
    const float* wk    = (const float*)d_in[4];
    const float* wv    = (const float*)d_in[5];
    const float* wo    = (const float*)d_in[6];
    float* out = (float*)d_out;

    const int smem_bytes = 24688 + NB * SQ * RS * 4;   // 104656 B -> 2 CTAs/SM

    cudaFuncSetAttribute(mha_fused_kernel,
                         cudaFuncAttributeMaxDynamicSharedMemorySize, smem_bytes);

    int nbatch = in_sizes[0] / (SQ * 8);            // 4096
    int grid = (nbatch + NB - 1) / NB;              // 586
    mha_fused_kernel<<<grid, NT, smem_bytes>>>(query, key, value, wq, wk, wv, wo,
                                               out, nbatch);
}